// round 3
// baseline (speedup 1.0000x reference)
#include <cuda_runtime.h>
#include <math.h>
#include <stdint.h>

// Problem constants
#define NN      10000
#define EE      320000
#define EALL    (EE + NN)     // edges + self loops = 330000
#define DIN     128
#define HDIM    64
#define NHEADS  4
#define BGRAPH  64
#define NEDGES_OUT 1024

// ---------------- scratch (static device globals; no runtime alloc) ----------------
__device__ __align__(16) float g_h  [NN * 256];   // post-linear features (pre-bias)
__device__ __align__(16) float g_o1 [NN * 256];   // layer1 output
__device__ __align__(16) float g_o2 [NN * 256];   // layer2 output
__device__ __align__(16) float g_o3 [NN * 64];    // layer3 output
__device__ float g_s  [NN * NHEADS];
__device__ float g_dt [NN * NHEADS];
__device__ int   g_deg[NN + 1];
__device__ int   g_ptr[NN + 1];
__device__ int   g_cur[NN];
__device__ int   g_csr[EALL];
__device__ float g_pool[BGRAPH * 64];
__device__ int   g_cnt [BGRAPH];

// ---------------- CSR build ----------------
__global__ void zero_deg_kernel() {
    int i = blockIdx.x * blockDim.x + threadIdx.x;
    if (i <= NN) g_deg[i] = 0;
}

// edge_index delivered as int32: row 0 = src at [0,EE), row 1 = dst at [EE,2*EE)
__global__ void count_deg_kernel(const int* __restrict__ ei) {
    int e = blockIdx.x * blockDim.x + threadIdx.x;
    if (e >= EALL) return;
    int dst = (e < EE) ? ei[EE + e] : (e - EE);
    atomicAdd(&g_deg[dst], 1);
}

// single-block exclusive scan of g_deg[0..NN-1] -> g_ptr[0..NN]
__global__ void scan_kernel() {
    __shared__ int sh[1024];
    const int t = threadIdx.x;
    const int PER = (NN + 1023) / 1024;
    int start = t * PER;
    int sum = 0;
    for (int i = 0; i < PER; i++) {
        int idx = start + i;
        if (idx < NN) sum += g_deg[idx];
    }
    sh[t] = sum;
    __syncthreads();
    for (int off = 1; off < 1024; off <<= 1) {
        int v = (t >= off) ? sh[t - off] : 0;
        __syncthreads();
        sh[t] += v;
        __syncthreads();
    }
    int run = (t == 0) ? 0 : sh[t - 1];
    for (int i = 0; i < PER; i++) {
        int idx = start + i;
        if (idx < NN) { g_ptr[idx] = run; run += g_deg[idx]; }
    }
    if (t == 1023) g_ptr[NN] = sh[1023];
}

__global__ void copy_cursor_kernel() {
    int i = blockIdx.x * blockDim.x + threadIdx.x;
    if (i < NN) g_cur[i] = g_ptr[i];
}

__global__ void scatter_kernel(const int* __restrict__ ei) {
    int e = blockIdx.x * blockDim.x + threadIdx.x;
    if (e >= EALL) return;
    int src, dst;
    if (e < EE) { src = ei[e]; dst = ei[EE + e]; }
    else        { src = e - EE; dst = e - EE; }
    int pos = atomicAdd(&g_cur[dst], 1);
    g_csr[pos] = src;
}

// ---------------- SGEMM: g_h[M,Ncol] = A[M,K] @ W[K,Ncol] ----------------
// asel: 0 -> A = Aext (external input x), 1 -> A = g_o1, 2 -> A = g_o2
__global__ void sgemm64_kernel(const float* __restrict__ Aext, int asel,
                               const float* __restrict__ W,
                               int M, int K, int Ncol) {
    const float* __restrict__ A = (asel == 0) ? Aext : (asel == 1 ? (const float*)g_o1
                                                                  : (const float*)g_o2);
    float* __restrict__ C = g_h;
    __shared__ float sA[64][17];
    __shared__ float sB[16][64];
    const int t  = threadIdx.x;       // 256 threads
    const int tx = t & 15, ty = t >> 4;
    const int brow = blockIdx.y * 64, bcol = blockIdx.x * 64;
    const int la_r = t >> 2, la_c = (t & 3) * 4;
    const int lb_r = t >> 4, lb_c = (t & 15) * 4;
    float acc[4][4] = {};
    for (int k0 = 0; k0 < K; k0 += 16) {
        int ar = brow + la_r;
        float4 av = make_float4(0.f, 0.f, 0.f, 0.f);
        if (ar < M) av = *reinterpret_cast<const float4*>(A + (size_t)ar * K + k0 + la_c);
        sA[la_r][la_c + 0] = av.x; sA[la_r][la_c + 1] = av.y;
        sA[la_r][la_c + 2] = av.z; sA[la_r][la_c + 3] = av.w;
        float4 bv = *reinterpret_cast<const float4*>(W + (size_t)(k0 + lb_r) * Ncol + bcol + lb_c);
        *reinterpret_cast<float4*>(&sB[lb_r][lb_c]) = bv;
        __syncthreads();
#pragma unroll
        for (int kk = 0; kk < 16; kk++) {
            float ar_[4], br_[4];
#pragma unroll
            for (int i = 0; i < 4; i++) ar_[i] = sA[ty * 4 + i][kk];
#pragma unroll
            for (int j = 0; j < 4; j++) br_[j] = sB[kk][tx * 4 + j];
#pragma unroll
            for (int i = 0; i < 4; i++)
#pragma unroll
                for (int j = 0; j < 4; j++) acc[i][j] += ar_[i] * br_[j];
        }
        __syncthreads();
    }
#pragma unroll
    for (int i = 0; i < 4; i++) {
        int r = brow + ty * 4 + i;
        if (r < M) {
#pragma unroll
            for (int j = 0; j < 4; j++)
                C[(size_t)r * Ncol + bcol + tx * 4 + j] = acc[i][j];
        }
    }
}

// ---------------- attention s/d per node (one block per node, H warps) ----------------
template <int H>
__global__ void attn_sd_kernel(const float* __restrict__ as_, const float* __restrict__ ad_) {
    const int C = H * 64;
    int v = blockIdx.x;
    int lane = threadIdx.x & 31, w = threadIdx.x >> 5;  // w < H
    const float* hp = g_h + (size_t)v * C + w * 64;
    float a1 = as_[w * 64 + lane], a2 = as_[w * 64 + lane + 32];
    float d1 = ad_[w * 64 + lane], d2 = ad_[w * 64 + lane + 32];
    float h1 = hp[lane], h2 = hp[lane + 32];
    float sv = h1 * a1 + h2 * a2;
    float dv = h1 * d1 + h2 * d2;
    for (int o = 16; o > 0; o >>= 1) {
        sv += __shfl_xor_sync(0xffffffffu, sv, o);
        dv += __shfl_xor_sync(0xffffffffu, dv, o);
    }
    if (lane == 0) { g_s[v * H + w] = sv; g_dt[v * H + w] = dv; }
}

// ---------------- GAT aggregation: one block per dst node ----------------
// osel: 1 -> out = g_o1, 2 -> g_o2, 3 -> g_o3. Input features are always g_h.
template <int H, int C>  // C = H*64 channels, block = C threads
__global__ void gat_agg_kernel(const float* __restrict__ bias, int osel) {
    const float* __restrict__ hmat = g_h;
    float* __restrict__ outp = (osel == 1) ? g_o1 : (osel == 2 ? g_o2 : g_o3);
    const int v = blockIdx.x;
    const int t = threadIdx.x;
    const int lane = t & 31, warp = t >> 5;
    const int hd = t / 64;
    const int p0 = g_ptr[v];
    const int deg = g_ptr[v + 1] - p0;
    __shared__ float sh_m[H], sh_ws[H];
    __shared__ int   sh_src[C];
    __shared__ float sh_w[C * H];

    if (warp < H) {
        float dv = g_dt[v * H + warp];
        float mx = -1e30f;
        for (int e = lane; e < deg; e += 32) {
            int sN = g_csr[p0 + e];
            float z = g_s[sN * H + warp] + dv;
            z = z > 0.f ? z : 0.2f * z;
            mx = fmaxf(mx, z);
        }
        for (int o = 16; o > 0; o >>= 1) mx = fmaxf(mx, __shfl_xor_sync(0xffffffffu, mx, o));
        float sum = 0.f;
        for (int e = lane; e < deg; e += 32) {
            int sN = g_csr[p0 + e];
            float z = g_s[sN * H + warp] + dv;
            z = z > 0.f ? z : 0.2f * z;
            sum += __expf(z - mx);
        }
        for (int o = 16; o > 0; o >>= 1) sum += __shfl_xor_sync(0xffffffffu, sum, o);
        if (lane == 0) { sh_m[warp] = mx; sh_ws[warp] = sum; }
    }
    __syncthreads();

    float acc = 0.f;
    for (int base = 0; base < deg; base += C) {
        int cnt = min(C, deg - base);
        if (t < cnt) {
            int sN = g_csr[p0 + base + t];
            sh_src[t] = sN;
#pragma unroll
            for (int hh = 0; hh < H; hh++) {
                float z = g_s[sN * H + hh] + g_dt[v * H + hh];
                z = z > 0.f ? z : 0.2f * z;
                sh_w[t * H + hh] = __expf(z - sh_m[hh]);
            }
        }
        __syncthreads();
        int e = 0;
        for (; e + 3 < cnt; e += 4) {
            float w0 = sh_w[(e + 0) * H + hd], w1 = sh_w[(e + 1) * H + hd];
            float w2 = sh_w[(e + 2) * H + hd], w3 = sh_w[(e + 3) * H + hd];
            float h0 = hmat[(size_t)sh_src[e + 0] * C + t];
            float h1 = hmat[(size_t)sh_src[e + 1] * C + t];
            float h2 = hmat[(size_t)sh_src[e + 2] * C + t];
            float h3 = hmat[(size_t)sh_src[e + 3] * C + t];
            acc += w0 * h0 + w1 * h1 + w2 * h2 + w3 * h3;
        }
        for (; e < cnt; e++) acc += sh_w[e * H + hd] * hmat[(size_t)sh_src[e] * C + t];
        __syncthreads();
    }
    float o = acc / sh_ws[hd] + bias[t];
    outp[(size_t)v * C + t] = fmaxf(o, 0.f);
}

// ---------------- pooling ----------------
__global__ void zero_pool_kernel() {
    int i = blockIdx.x * blockDim.x + threadIdx.x;
    if (i < BGRAPH * 64) g_pool[i] = 0.f;
    if (i < BGRAPH) g_cnt[i] = 0;
}

__global__ void count_nodes_kernel(const int* __restrict__ batch) {
    int n = blockIdx.x * blockDim.x + threadIdx.x;
    if (n < NN) atomicAdd(&g_cnt[batch[n]], 1);
}

__global__ void pool_sum_kernel(const int* __restrict__ batch) {
    int gid = blockIdx.x * blockDim.x + threadIdx.x;
    if (gid >= NN * 64) return;
    int n = gid >> 6, c = gid & 63;
    atomicAdd(&g_pool[batch[n] * 64 + c], g_o3[gid]);
}

// ---------------- actor / critic heads ----------------
__global__ void heads_kernel(const float* __restrict__ Wa1, const float* __restrict__ ba1,
                             const float* __restrict__ Wa2, const float* __restrict__ ba2,
                             const float* __restrict__ Wc1, const float* __restrict__ bc1,
                             const float* __restrict__ Wc2, const float* __restrict__ bc2,
                             float* __restrict__ out) {
    int b = blockIdx.x;
    int t = threadIdx.x;
    __shared__ float p[64], ha[64], hc[64];
    if (t < 64) {
        int c = g_cnt[b];
        float cc = c > 0 ? (float)c : 1.f;
        p[t] = g_pool[b * 64 + t] / cc;
    }
    __syncthreads();
    if (t < 64) {
        float aa = ba1[t], cv = bc1[t];
        for (int j = 0; j < 64; j++) { aa += p[j] * Wa1[j * 64 + t]; cv += p[j] * Wc1[j * 64 + t]; }
        ha[t] = fmaxf(aa, 0.f);
        hc[t] = fmaxf(cv, 0.f);
    }
    __syncthreads();
    for (int o = t; o < NEDGES_OUT; o += blockDim.x) {
        float acc = ba2[o];
        for (int j = 0; j < 64; j++) acc += ha[j] * Wa2[j * NEDGES_OUT + o];
        out[b * NEDGES_OUT + o] = tanhf(acc);
    }
    if (t == 0) {
        float acc = bc2[0];
        for (int j = 0; j < 64; j++) acc += hc[j] * Wc2[j];
        out[BGRAPH * NEDGES_OUT + b] = acc;
    }
}

// ---------------- launch ----------------
extern "C" void kernel_launch(void* const* d_in, const int* in_sizes, int n_in,
                              void* d_out, int out_size) {
    const float* x     = (const float*)d_in[0];
    const int*   ei    = (const int*)d_in[1];
    const int*   batch = (const int*)d_in[2];
    const float* W1  = (const float*)d_in[3];
    const float* as1 = (const float*)d_in[4];
    const float* ad1 = (const float*)d_in[5];
    const float* b1  = (const float*)d_in[6];
    const float* W2  = (const float*)d_in[7];
    const float* as2 = (const float*)d_in[8];
    const float* ad2 = (const float*)d_in[9];
    const float* b2  = (const float*)d_in[10];
    const float* W3  = (const float*)d_in[11];
    const float* as3 = (const float*)d_in[12];
    const float* ad3 = (const float*)d_in[13];
    const float* b3  = (const float*)d_in[14];
    const float* Wa1 = (const float*)d_in[15];
    const float* ba1 = (const float*)d_in[16];
    const float* Wa2 = (const float*)d_in[17];
    const float* ba2 = (const float*)d_in[18];
    const float* Wc1 = (const float*)d_in[19];
    const float* bc1 = (const float*)d_in[20];
    const float* Wc2 = (const float*)d_in[21];
    const float* bc2 = (const float*)d_in[22];
    float* out = (float*)d_out;

    // CSR build (same graph for all 3 layers)
    zero_deg_kernel<<<(NN + 256) / 256, 256>>>();
    count_deg_kernel<<<(EALL + 255) / 256, 256>>>(ei);
    scan_kernel<<<1, 1024>>>();
    copy_cursor_kernel<<<(NN + 255) / 256, 256>>>();
    scatter_kernel<<<(EALL + 255) / 256, 256>>>(ei);

    const int MB = (NN + 63) / 64;  // 157

    // Layer 1: in=128, heads=4, out-concat=256
    sgemm64_kernel<<<dim3(4, MB), 256>>>(x, 0, W1, NN, 128, 256);
    attn_sd_kernel<4><<<NN, 128>>>(as1, ad1);
    gat_agg_kernel<4, 256><<<NN, 256>>>(b1, 1);

    // Layer 2: in=256, heads=4, out-concat=256
    sgemm64_kernel<<<dim3(4, MB), 256>>>(x, 1, W2, NN, 256, 256);
    attn_sd_kernel<4><<<NN, 128>>>(as2, ad2);
    gat_agg_kernel<4, 256><<<NN, 256>>>(b2, 2);

    // Layer 3: in=256, heads=1, out=64 (mean over 1 head)
    sgemm64_kernel<<<dim3(1, MB), 256>>>(x, 2, W3, NN, 256, 64);
    attn_sd_kernel<1><<<NN, 32>>>(as3, ad3);
    gat_agg_kernel<1, 64><<<NN, 64>>>(b3, 3);

    // global mean pool + heads
    zero_pool_kernel<<<(BGRAPH * 64 + 255) / 256, 256>>>();
    count_nodes_kernel<<<(NN + 255) / 256, 256>>>(batch);
    pool_sum_kernel<<<(NN * 64 + 255) / 256, 256>>>(batch);
    heads_kernel<<<BGRAPH, 256>>>(Wa1, ba1, Wa2, ba2, Wc1, bc1, Wc2, bc2, out);
}